// round 14
// baseline (speedup 1.0000x reference)
#include <cuda_runtime.h>

#define A_DIM 1024
#define T_DIM 256
#define CS 384
#define CZ 128
#define CA 128
#define CP 16
#define EPS 1e-5f

// ---- device scratch ----
__device__ int   g_tok[A_DIM];
__device__ float g_ys[T_DIM * CA];
__device__ float g_w[T_DIM * T_DIM * CP];

#define FMA2(d, a, b) asm("fma.rn.f32x2 %0, %1, %2, %0;" : "+l"(d) : "l"(a), "l"(b))
#define ADD2(d, a)    asm("add.rn.f32x2 %0, %0, %1;" : "+l"(d) : "l"(a))

__device__ __forceinline__ float hsum2(unsigned long long v) {
    float lo, hi;
    asm("mov.b64 {%0, %1}, %2;" : "=f"(lo), "=f"(hi) : "l"(v));
    return lo + hi;
}

#define YS_BLOCKS 32
#define TOK_BLOCKS 32
#define KW_BLOCKS 1024    // 64 rows each (1 row per thread)
#define GWPAD 132

// ================= kernel A (round-9 champion) =================
__global__ __launch_bounds__(256) void kernelA(
    const float* __restrict__ zij, const float* __restrict__ gz,
    const float* __restrict__ bz, const float* __restrict__ Wz,
    const float* __restrict__ s_trunk, const float* __restrict__ gs,
    const float* __restrict__ bs, const float* __restrict__ Ws,
    const float* __restrict__ a2t) {
    asm volatile("griddepcontrol.launch_dependents;");
    int tid = threadIdx.x;
    int bx = blockIdx.x;

    if (bx < YS_BLOCKS) {
        __shared__ float sn[8][CS];
        __shared__ float mv[8][2];
        int t0 = bx * 8;
        int w = tid >> 5, lane = tid & 31;
        {
            int t = t0 + w;
            float s1 = 0.f, s2 = 0.f;
#pragma unroll
            for (int i = 0; i < 12; i++) {
                int k = lane + 32 * i;
                float x = s_trunk[(size_t)t * CS + k];
                sn[w][k] = x;
                s1 += x;
                s2 = fmaf(x, x, s2);
            }
            for (int d = 16; d; d >>= 1) {
                s1 += __shfl_down_sync(0xffffffffu, s1, d);
                s2 += __shfl_down_sync(0xffffffffu, s2, d);
            }
            if (lane == 0) {
                float m = s1 * (1.0f / CS);
                float v = s2 * (1.0f / CS) - m * m;
                mv[w][0] = m;
                mv[w][1] = rsqrtf(v + EPS);
            }
        }
        __syncthreads();
#pragma unroll
        for (int i = 0; i < 12; i++) {
            int idx = tid + 256 * i;
            int r = idx / CS, k = idx - r * CS;
            sn[r][k] = (sn[r][k] - mv[r][0]) * mv[r][1] * gs[k] + bs[k];
        }
        __syncthreads();
        int j = tid & 127;
        int h = tid >> 7;
        float a0 = 0.f, a1 = 0.f, a2 = 0.f, a3 = 0.f;
#pragma unroll 16
        for (int k = 0; k < CS; k++) {
            float wv = Ws[(size_t)k * CA + j];
            a0 = fmaf(sn[4*h  ][k], wv, a0);
            a1 = fmaf(sn[4*h+1][k], wv, a1);
            a2 = fmaf(sn[4*h+2][k], wv, a2);
            a3 = fmaf(sn[4*h+3][k], wv, a3);
        }
        g_ys[(size_t)(t0 + 4*h    ) * CA + j] = a0;
        g_ys[(size_t)(t0 + 4*h + 1) * CA + j] = a1;
        g_ys[(size_t)(t0 + 4*h + 2) * CA + j] = a2;
        g_ys[(size_t)(t0 + 4*h + 3) * CA + j] = a3;
        return;
    }

    if (bx < YS_BLOCKS + TOK_BLOCKS) {
        int row0 = (bx - YS_BLOCKS) * 32;
#pragma unroll
        for (int i = 0; i < 32; i++) {
            float v = a2t[(size_t)(row0 + i) * T_DIM + tid];
            if (v > 0.5f) g_tok[row0 + i] = tid;
        }
        return;
    }

    // ---------- k_w: 64 rows per block, 1 row per thread ----------
    __shared__ __align__(16) float GWs[CP * GWPAD];
    __shared__ float BWs[CP], CgWs[CP];
    __shared__ float pbw[256], pcg[256];
    {
        int j = tid & 15;
        float pb = 0.f, pc = 0.f;
#pragma unroll
        for (int i = 0; i < 8; i++) {
            int idx = tid + 256 * i;
            int k = idx >> 4;
            float wv = Wz[idx];
            float gw = gz[k] * wv;
            GWs[j * GWPAD + k] = gw;
            pb = fmaf(bz[k], wv, pb);
            pc += gw;
        }
        pbw[tid] = pb;
        pcg[tid] = pc;
    }
    __syncthreads();
    if (tid < CP) {
        float sb = 0.f, sc = 0.f;
#pragma unroll
        for (int i = 0; i < 16; i++) {
            sb += pbw[tid + 16 * i];
            sc += pcg[tid + 16 * i];
        }
        BWs[tid] = sb;
        CgWs[tid] = sc;
    }
    __syncthreads();

    int q = tid & 3, rp = tid >> 2;
    size_t row = (size_t)(bx - YS_BLOCKS - TOK_BLOCKS) * 64 + rp;
    const ulonglong2* z = (const ulonglong2*)(zij + row * CZ);
    const ulonglong2* G = (const ulonglong2*)GWs;

    unsigned long long acc[CP];
#pragma unroll
    for (int j = 0; j < CP; j++) acc[j] = 0ull;
    unsigned long long sS = 0ull, sQ = 0ull;

#pragma unroll
    for (int c = 0; c < 8; c++) {
        ulonglong2 zv = __ldcs(&z[q + 4 * c]);
        ADD2(sS, zv.x); ADD2(sS, zv.y);
        FMA2(sQ, zv.x, zv.x); FMA2(sQ, zv.y, zv.y);
#pragma unroll
        for (int j = 0; j < CP; j++) {
            ulonglong2 g = G[j * 33 + q + 4 * c];
            FMA2(acc[j], zv.x, g.x); FMA2(acc[j], zv.y, g.y);
        }
    }

    float s1 = hsum2(sS), s2 = hsum2(sQ);
    s1 += __shfl_xor_sync(0xffffffffu, s1, 1);
    s2 += __shfl_xor_sync(0xffffffffu, s2, 1);
    s1 += __shfl_xor_sync(0xffffffffu, s1, 2);
    s2 += __shfl_xor_sync(0xffffffffu, s2, 2);
    float m  = s1 * (1.0f / CZ);
    float vv = s2 * (1.0f / CZ) - m * m;
    float ri = rsqrtf(vv + EPS);

    float f[16];
#pragma unroll
    for (int j = 0; j < CP; j++) f[j] = hsum2(acc[j]);

    bool hi = (q & 1);
    float kk[8];
#pragma unroll
    for (int i = 0; i < 8; i++) {
        float lo = f[i], hih = f[8 + i];
        float mine = hi ? hih : lo;
        float send = hi ? lo : hih;
        kk[i] = mine + __shfl_xor_sync(0xffffffffu, send, 1);
    }
    bool hi2 = (q & 2);
    float g4[4];
#pragma unroll
    for (int i = 0; i < 4; i++) {
        float lo = kk[i], hih = kk[4 + i];
        float mine = hi2 ? hih : lo;
        float send = hi2 ? lo : hih;
        g4[i] = mine + __shfl_xor_sync(0xffffffffu, send, 2);
    }
    int jb = (hi ? 8 : 0) + (hi2 ? 4 : 0);

    float4 o;
    o.x = ri * (g4[0] - m * CgWs[jb    ]) + BWs[jb    ];
    o.y = ri * (g4[1] - m * CgWs[jb + 1]) + BWs[jb + 1];
    o.z = ri * (g4[2] - m * CgWs[jb + 2]) + BWs[jb + 2];
    o.w = ri * (g4[3] - m * CgWs[jb + 3]) + BWs[jb + 3];
    *((float4*)(g_w + row * CP + jb)) = o;
}

// ================= kernel B (round-9 champion, unchanged) =================
__global__ __launch_bounds__(256) void kernelB(
    const float* __restrict__ cl, const float* __restrict__ ql,
    const float* __restrict__ rl, const float* __restrict__ Wr,
    const float* __restrict__ plm,
    float* __restrict__ out_cl, float* __restrict__ out_ql,
    float* __restrict__ out_plm) {
    int tid = threadIdx.x;
    int bx = blockIdx.x;

    if (bx < 128) {
        int a = bx * 8 + (tid >> 5);
        int j4 = tid & 31;
        size_t idx = (size_t)a * 32 + j4;
        const float4* cl4 = (const float4*)cl;
        const float4* ql4 = (const float4*)ql;
        const float4* ys4 = (const float4*)g_ys;
        const float4* Wr4 = (const float4*)Wr;
        float4 c = cl4[idx];
        float4 qv = ql4[idx];
        float r0 = rl[a * 3], r1 = rl[a * 3 + 1], r2 = rl[a * 3 + 2];
        float4 w0 = Wr4[j4], w1 = Wr4[32 + j4], w2 = Wr4[64 + j4];
        float4 oq;
        oq.x = qv.x + r0 * w0.x + r1 * w1.x + r2 * w2.x;
        oq.y = qv.y + r0 * w0.y + r1 * w1.y + r2 * w2.y;
        oq.z = qv.z + r0 * w0.z + r1 * w1.z + r2 * w2.z;
        oq.w = qv.w + r0 * w0.w + r1 * w1.w + r2 * w2.w;
        ((float4*)out_ql)[idx] = oq;
        asm volatile("griddepcontrol.wait;" ::: "memory");
        int ta = g_tok[a];
        float4 y = ys4[(size_t)ta * 32 + j4];
        float4 oc;
        oc.x = c.x + y.x; oc.y = c.y + y.y; oc.z = c.z + y.z; oc.w = c.w + y.w;
        ((float4*)out_cl)[idx] = oc;
        return;
    }

    int pm = bx - 128;
    int a0 = (pm >> 4) * 8;
    int b = (pm & 15) * 64 + (tid >> 2);
    int c4 = tid & 3;
    const float4* p4 = (const float4*)plm;
    const float4* w4 = (const float4*)g_w;
    float4* o4 = (float4*)out_plm;

    float4 p[8];
#pragma unroll
    for (int i = 0; i < 8; i++)
        p[i] = __ldcs(&p4[((size_t)(a0 + i) * A_DIM + b) * 4 + c4]);

    asm volatile("griddepcontrol.wait;" ::: "memory");

    int tb = g_tok[b];
    int ta[8];
#pragma unroll
    for (int i = 0; i < 8; i++) ta[i] = g_tok[a0 + i];

    float4 w[8];
#pragma unroll
    for (int i = 0; i < 8; i++)
        w[i] = w4[((size_t)ta[i] * T_DIM + tb) * 4 + c4];
#pragma unroll
    for (int i = 0; i < 8; i++) {
        float4 o;
        o.x = p[i].x + w[i].x; o.y = p[i].y + w[i].y;
        o.z = p[i].z + w[i].z; o.w = p[i].w + w[i].w;
        __stcs(&o4[((size_t)(a0 + i) * A_DIM + b) * 4 + c4], o);
    }
}

extern "C" void kernel_launch(void* const* d_in, const int* in_sizes, int n_in,
                              void* d_out, int out_size) {
    const float* a2t     = (const float*)d_in[0];
    const float* cl      = (const float*)d_in[1];
    const float* plm     = (const float*)d_in[2];
    const float* ql      = (const float*)d_in[3];
    const float* s_trunk = (const float*)d_in[4];
    const float* zij     = (const float*)d_in[5];
    const float* rl      = (const float*)d_in[6];
    const float* ln_s_g  = (const float*)d_in[7];
    const float* ln_s_b  = (const float*)d_in[8];
    const float* Ws      = (const float*)d_in[9];
    const float* ln_z_g  = (const float*)d_in[10];
    const float* ln_z_b  = (const float*)d_in[11];
    const float* Wz      = (const float*)d_in[12];
    const float* Wr      = (const float*)d_in[13];
    float* out     = (float*)d_out;
    float* out_cl  = out;
    float* out_plm = out + A_DIM * CA;
    float* out_ql  = out_plm + (size_t)A_DIM * A_DIM * CP;

    kernelA<<<YS_BLOCKS + TOK_BLOCKS + KW_BLOCKS, 256>>>(
        zij, ln_z_g, ln_z_b, Wz, s_trunk, ln_s_g, ln_s_b, Ws, a2t);

    {
        cudaLaunchConfig_t cfg = {};
        cfg.gridDim = dim3(128 + 2048);
        cfg.blockDim = dim3(256);
        cfg.dynamicSmemBytes = 0;
        cfg.stream = 0;
        cudaLaunchAttribute attrs[1];
        attrs[0].id = cudaLaunchAttributeProgrammaticStreamSerialization;
        attrs[0].val.programmaticStreamSerializationAllowed = 1;
        cfg.attrs = attrs;
        cfg.numAttrs = 1;
        cudaLaunchKernelEx(&cfg, kernelB, cl, ql, rl, Wr, plm,
                           out_cl, out_ql, out_plm);
    }

    // DIAGNOSTIC (this round only): re-run kernelA as the LAST node.
    // It is idempotent (rewrites g_w/g_ys/g_tok with identical values), so
    // outputs are unchanged — but ncu's capture lands on the last kernel,
    // finally giving us kernelA's roofline, measured solo.
    kernelA<<<YS_BLOCKS + TOK_BLOCKS + KW_BLOCKS, 256>>>(
        zij, ln_z_g, ln_z_b, Wz, s_trunk, ln_s_g, ln_s_b, Ws, a2t);
}

// round 15
// speedup vs baseline: 1.5094x; 1.5094x over previous
#include <cuda_runtime.h>

#define A_DIM 1024
#define T_DIM 256
#define CS 384
#define CZ 128
#define CA 128
#define CP 16
#define EPS 1e-5f

// ---- device scratch ----
__device__ int   g_tok[A_DIM];
__device__ float g_ys[T_DIM * CA];
__device__ float g_w[T_DIM * T_DIM * CP];

#define FMA2(d, a, b) asm("fma.rn.f32x2 %0, %1, %2, %0;" : "+l"(d) : "l"(a), "l"(b))
#define ADD2(d, a)    asm("add.rn.f32x2 %0, %0, %1;" : "+l"(d) : "l"(a))

__device__ __forceinline__ float hsum2(unsigned long long v) {
    float lo, hi;
    asm("mov.b64 {%0, %1}, %2;" : "=f"(lo), "=f"(hi) : "l"(v));
    return lo + hi;
}

#define YS_BLOCKS 32
#define TOK_BLOCKS 32
#define KW_ROWS 32
#define KW_BLOCKS 2048    // 32 rows each
#define GWPAD 132

// ================= kernel A =================
// blocks [0,32)     : ys (8 tokens each)
// blocks [32,64)    : tok recovery
// blocks [64,2112)  : k_w, 32 rows; warp = k-eighth (GW warp-uniform), lane = row
__global__ __launch_bounds__(256) void kernelA(
    const float* __restrict__ zij, const float* __restrict__ gz,
    const float* __restrict__ bz, const float* __restrict__ Wz,
    const float* __restrict__ s_trunk, const float* __restrict__ gs,
    const float* __restrict__ bs, const float* __restrict__ Ws,
    const float* __restrict__ a2t) {
    asm volatile("griddepcontrol.launch_dependents;");
    int tid = threadIdx.x;
    int bx = blockIdx.x;

    if (bx < YS_BLOCKS) {
        __shared__ float sn[8][CS];
        __shared__ float mv[8][2];
        int t0 = bx * 8;
        int w = tid >> 5, lane = tid & 31;
        {
            int t = t0 + w;
            float s1 = 0.f, s2 = 0.f;
#pragma unroll
            for (int i = 0; i < 12; i++) {
                int k = lane + 32 * i;
                float x = s_trunk[(size_t)t * CS + k];
                sn[w][k] = x;
                s1 += x;
                s2 = fmaf(x, x, s2);
            }
            for (int d = 16; d; d >>= 1) {
                s1 += __shfl_down_sync(0xffffffffu, s1, d);
                s2 += __shfl_down_sync(0xffffffffu, s2, d);
            }
            if (lane == 0) {
                float m = s1 * (1.0f / CS);
                float v = s2 * (1.0f / CS) - m * m;
                mv[w][0] = m;
                mv[w][1] = rsqrtf(v + EPS);
            }
        }
        __syncthreads();
#pragma unroll
        for (int i = 0; i < 12; i++) {
            int idx = tid + 256 * i;
            int r = idx / CS, k = idx - r * CS;
            sn[r][k] = (sn[r][k] - mv[r][0]) * mv[r][1] * gs[k] + bs[k];
        }
        __syncthreads();
        int j = tid & 127;
        int h = tid >> 7;
        float a0 = 0.f, a1 = 0.f, a2 = 0.f, a3 = 0.f;
#pragma unroll 16
        for (int k = 0; k < CS; k++) {
            float wv = Ws[(size_t)k * CA + j];
            a0 = fmaf(sn[4*h  ][k], wv, a0);
            a1 = fmaf(sn[4*h+1][k], wv, a1);
            a2 = fmaf(sn[4*h+2][k], wv, a2);
            a3 = fmaf(sn[4*h+3][k], wv, a3);
        }
        g_ys[(size_t)(t0 + 4*h    ) * CA + j] = a0;
        g_ys[(size_t)(t0 + 4*h + 1) * CA + j] = a1;
        g_ys[(size_t)(t0 + 4*h + 2) * CA + j] = a2;
        g_ys[(size_t)(t0 + 4*h + 3) * CA + j] = a3;
        return;
    }

    if (bx < YS_BLOCKS + TOK_BLOCKS) {
        int row0 = (bx - YS_BLOCKS) * 32;
#pragma unroll
        for (int i = 0; i < 32; i++) {
            float v = a2t[(size_t)(row0 + i) * T_DIM + tid];
            if (v > 0.5f) g_tok[row0 + i] = tid;
        }
        return;
    }

    // ---------- k_w: 32 rows/block; warp w owns k-slice [w*16, w*16+16) ----------
    __shared__ __align__(16) float GWs[CP * GWPAD];        // 8.4 KB  [j][k]
    __shared__ __align__(16) float zs[KW_ROWS * GWPAD];    // 16.9 KB [row][k]
    __shared__ float rst[18][8][32];                       // 18 KB   [item][q8][row]
    __shared__ float BWs[CP], CgWs[CP];
    __shared__ float osm[KW_ROWS * 18];                    // 2.25 KB out stage

    // phase 0: GW + folded constants (pbw/pcg staged in rst space)
    {
        float* pbw = &rst[0][0][0];
        float* pcg = pbw + 256;
        int j = tid & 15;
        float pb = 0.f, pc = 0.f;
#pragma unroll
        for (int i = 0; i < 8; i++) {
            int idx = tid + 256 * i;
            int k = idx >> 4;
            float wv = Wz[idx];
            float gw = gz[k] * wv;
            GWs[j * GWPAD + k] = gw;
            pb = fmaf(bz[k], wv, pb);
            pc += gw;
        }
        pbw[tid] = pb;
        pcg[tid] = pc;
        __syncthreads();
        if (tid < CP) {
            float sb = 0.f, sc = 0.f;
#pragma unroll
            for (int i = 0; i < 16; i++) {
                sb += pbw[tid + 16 * i];
                sc += pcg[tid + 16 * i];
            }
            BWs[tid] = sb;
            CgWs[tid] = sc;
        }
    }

    // phase 1: stage z tile (32 rows x 128 floats), coalesced streaming loads
    {
        size_t row0 = (size_t)(bx - YS_BLOCKS - TOK_BLOCKS) * KW_ROWS;
        const float4* zg = (const float4*)(zij + row0 * CZ);
        float4* zs4 = (float4*)zs;
#pragma unroll
        for (int i = 0; i < 4; i++) {
            int idx = tid + 256 * i;            // 0..1023
            int r = idx >> 5, c16 = idx & 31;
            zs4[r * 33 + c16] = __ldcs(&zg[idx]);
        }
    }
    __syncthreads();

    // phase 2: warp w = k-eighth (chunks w*4..w*4+3), lane = row
    {
        int w = tid >> 5, lane = tid & 31;
        const ulonglong2* zrow = (const ulonglong2*)(zs + lane * GWPAD);
        const ulonglong2* G = (const ulonglong2*)GWs;

        unsigned long long acc[CP];
#pragma unroll
        for (int j = 0; j < CP; j++) acc[j] = 0ull;
        unsigned long long sS = 0ull, sQ = 0ull;

#pragma unroll
        for (int c = 0; c < 4; c++) {
            int chunk = w * 4 + c;
            ulonglong2 zv = zrow[chunk];
            ADD2(sS, zv.x); ADD2(sS, zv.y);
            FMA2(sQ, zv.x, zv.x); FMA2(sQ, zv.y, zv.y);
#pragma unroll
            for (int j = 0; j < CP; j++) {
                ulonglong2 g = G[j * 33 + chunk];   // warp-uniform: true broadcast
                FMA2(acc[j], zv.x, g.x); FMA2(acc[j], zv.y, g.y);
            }
        }
        // stage partials: [item][q8=w][row=lane] — lane varies bank, conflict-free
#pragma unroll
        for (int j = 0; j < CP; j++) rst[j][w][lane] = hsum2(acc[j]);
        rst[16][w][lane] = hsum2(sS);
        rst[17][w][lane] = hsum2(sQ);
    }
    __syncthreads();

    // phase 3: reduce 8 k-slices; thread = (row = tid&31, jh = tid>>5 -> j = 2jh)
    {
        int row = tid & 31, jh = tid >> 5;
        float s1 = 0.f, s2 = 0.f, f0 = 0.f, f1 = 0.f;
#pragma unroll
        for (int q = 0; q < 8; q++) {
            f0 += rst[2*jh    ][q][row];
            f1 += rst[2*jh + 1][q][row];
            s1 += rst[16][q][row];
            s2 += rst[17][q][row];
        }
        float m  = s1 * (1.0f / CZ);
        float vv = s2 * (1.0f / CZ) - m * m;
        float ri = rsqrtf(vv + EPS);
        osm[row * 18 + 2*jh    ] = ri * (f0 - m * CgWs[2*jh    ]) + BWs[2*jh    ];
        osm[row * 18 + 2*jh + 1] = ri * (f1 - m * CgWs[2*jh + 1]) + BWs[2*jh + 1];
    }
    __syncthreads();

    // phase 4: coalesced write of 32x16 w tile
    {
        size_t row0 = (size_t)(bx - YS_BLOCKS - TOK_BLOCKS) * KW_ROWS;
        float2* wo = (float2*)(g_w + row0 * CP);
        int r = tid >> 3, jp = tid & 7;         // 256 threads = 32 rows x 8 float2
        float2 v;
        v.x = osm[r * 18 + jp * 2];
        v.y = osm[r * 18 + jp * 2 + 1];
        wo[r * 8 + jp] = v;
    }
}

// ================= kernel B (round-9 champion, unchanged) =================
__global__ __launch_bounds__(256) void kernelB(
    const float* __restrict__ cl, const float* __restrict__ ql,
    const float* __restrict__ rl, const float* __restrict__ Wr,
    const float* __restrict__ plm,
    float* __restrict__ out_cl, float* __restrict__ out_ql,
    float* __restrict__ out_plm) {
    int tid = threadIdx.x;
    int bx = blockIdx.x;

    if (bx < 128) {
        int a = bx * 8 + (tid >> 5);
        int j4 = tid & 31;
        size_t idx = (size_t)a * 32 + j4;
        const float4* cl4 = (const float4*)cl;
        const float4* ql4 = (const float4*)ql;
        const float4* ys4 = (const float4*)g_ys;
        const float4* Wr4 = (const float4*)Wr;
        float4 c = cl4[idx];
        float4 qv = ql4[idx];
        float r0 = rl[a * 3], r1 = rl[a * 3 + 1], r2 = rl[a * 3 + 2];
        float4 w0 = Wr4[j4], w1 = Wr4[32 + j4], w2 = Wr4[64 + j4];
        float4 oq;
        oq.x = qv.x + r0 * w0.x + r1 * w1.x + r2 * w2.x;
        oq.y = qv.y + r0 * w0.y + r1 * w1.y + r2 * w2.y;
        oq.z = qv.z + r0 * w0.z + r1 * w1.z + r2 * w2.z;
        oq.w = qv.w + r0 * w0.w + r1 * w1.w + r2 * w2.w;
        ((float4*)out_ql)[idx] = oq;
        asm volatile("griddepcontrol.wait;" ::: "memory");
        int ta = g_tok[a];
        float4 y = ys4[(size_t)ta * 32 + j4];
        float4 oc;
        oc.x = c.x + y.x; oc.y = c.y + y.y; oc.z = c.z + y.z; oc.w = c.w + y.w;
        ((float4*)out_cl)[idx] = oc;
        return;
    }

    int pm = bx - 128;
    int a0 = (pm >> 4) * 8;
    int b = (pm & 15) * 64 + (tid >> 2);
    int c4 = tid & 3;
    const float4* p4 = (const float4*)plm;
    const float4* w4 = (const float4*)g_w;
    float4* o4 = (float4*)out_plm;

    float4 p[8];
#pragma unroll
    for (int i = 0; i < 8; i++)
        p[i] = __ldcs(&p4[((size_t)(a0 + i) * A_DIM + b) * 4 + c4]);

    asm volatile("griddepcontrol.wait;" ::: "memory");

    int tb = g_tok[b];
    int ta[8];
#pragma unroll
    for (int i = 0; i < 8; i++) ta[i] = g_tok[a0 + i];

    float4 w[8];
#pragma unroll
    for (int i = 0; i < 8; i++)
        w[i] = w4[((size_t)ta[i] * T_DIM + tb) * 4 + c4];
#pragma unroll
    for (int i = 0; i < 8; i++) {
        float4 o;
        o.x = p[i].x + w[i].x; o.y = p[i].y + w[i].y;
        o.z = p[i].z + w[i].z; o.w = p[i].w + w[i].w;
        __stcs(&o4[((size_t)(a0 + i) * A_DIM + b) * 4 + c4], o);
    }
}

extern "C" void kernel_launch(void* const* d_in, const int* in_sizes, int n_in,
                              void* d_out, int out_size) {
    const float* a2t     = (const float*)d_in[0];
    const float* cl      = (const float*)d_in[1];
    const float* plm     = (const float*)d_in[2];
    const float* ql      = (const float*)d_in[3];
    const float* s_trunk = (const float*)d_in[4];
    const float* zij     = (const float*)d_in[5];
    const float* rl      = (const float*)d_in[6];
    const float* ln_s_g  = (const float*)d_in[7];
    const float* ln_s_b  = (const float*)d_in[8];
    const float* Ws      = (const float*)d_in[9];
    const float* ln_z_g  = (const float*)d_in[10];
    const float* ln_z_b  = (const float*)d_in[11];
    const float* Wz      = (const float*)d_in[12];
    const float* Wr      = (const float*)d_in[13];
    float* out     = (float*)d_out;
    float* out_cl  = out;
    float* out_plm = out + A_DIM * CA;
    float* out_ql  = out_plm + (size_t)A_DIM * A_DIM * CP;

    kernelA<<<YS_BLOCKS + TOK_BLOCKS + KW_BLOCKS, 256>>>(
        zij, ln_z_g, ln_z_b, Wz, s_trunk, ln_s_g, ln_s_b, Ws, a2t);

    {
        cudaLaunchConfig_t cfg = {};
        cfg.gridDim = dim3(128 + 2048);
        cfg.blockDim = dim3(256);
        cfg.dynamicSmemBytes = 0;
        cfg.stream = 0;
        cudaLaunchAttribute attrs[1];
        attrs[0].id = cudaLaunchAttributeProgrammaticStreamSerialization;
        attrs[0].val.programmaticStreamSerializationAllowed = 1;
        cfg.attrs = attrs;
        cfg.numAttrs = 1;
        cudaLaunchKernelEx(&cfg, kernelB, cl, ql, rl, Wr, plm,
                           out_cl, out_ql, out_plm);
    }
}

// round 16
// speedup vs baseline: 1.5165x; 1.0047x over previous
#include <cuda_runtime.h>

#define A_DIM 1024
#define T_DIM 256
#define CS 384
#define CZ 128
#define CA 128
#define CP 16
#define EPS 1e-5f

// ---- device scratch ----
__device__ int   g_tok[A_DIM];
__device__ float g_ys[T_DIM * CA];
__device__ float g_w[T_DIM * T_DIM * CP];

#define FMA2(d, a, b) asm("fma.rn.f32x2 %0, %1, %2, %0;" : "+l"(d) : "l"(a), "l"(b))
#define ADD2(d, a)    asm("add.rn.f32x2 %0, %0, %1;" : "+l"(d) : "l"(a))
#define PREFETCH_L2(p) asm volatile("prefetch.global.L2 [%0];" :: "l"(p))

__device__ __forceinline__ float hsum2(unsigned long long v) {
    float lo, hi;
    asm("mov.b64 {%0, %1}, %2;" : "=f"(lo), "=f"(hi) : "l"(v));
    return lo + hi;
}

#define YS_BLOCKS 32
#define TOK_BLOCKS 32
#define KW_ROWS 32
#define KW_BLOCKS 2048    // 32 rows each
#define GWPAD 132

// ================= kernel A =================
// blocks [0,32)     : ys (8 tokens each) + ql L2-prefetch
// blocks [32,64)    : tok recovery + cl L2-prefetch
// blocks [64,2112)  : k_w (32 rows) + plm L2-prefetch (1 cacheline/thread)
__global__ __launch_bounds__(256) void kernelA(
    const float* __restrict__ zij, const float* __restrict__ gz,
    const float* __restrict__ bz, const float* __restrict__ Wz,
    const float* __restrict__ s_trunk, const float* __restrict__ gs,
    const float* __restrict__ bs, const float* __restrict__ Ws,
    const float* __restrict__ a2t,
    const float* __restrict__ plm, const float* __restrict__ cl,
    const float* __restrict__ ql) {
    asm volatile("griddepcontrol.launch_dependents;");
    int tid = threadIdx.x;
    int bx = blockIdx.x;

    if (bx < YS_BLOCKS) {
        // prefetch ql into L2 (512 KB total = 4096 lines over 8192 threads)
        {
            int idx = bx * 256 + tid;
            if (idx < 4096) PREFETCH_L2(ql + (size_t)idx * 32);
        }
        __shared__ float sn[8][CS];
        __shared__ float mv[8][2];
        int t0 = bx * 8;
        int w = tid >> 5, lane = tid & 31;
        {
            int t = t0 + w;
            float s1 = 0.f, s2 = 0.f;
#pragma unroll
            for (int i = 0; i < 12; i++) {
                int k = lane + 32 * i;
                float x = s_trunk[(size_t)t * CS + k];
                sn[w][k] = x;
                s1 += x;
                s2 = fmaf(x, x, s2);
            }
            for (int d = 16; d; d >>= 1) {
                s1 += __shfl_down_sync(0xffffffffu, s1, d);
                s2 += __shfl_down_sync(0xffffffffu, s2, d);
            }
            if (lane == 0) {
                float m = s1 * (1.0f / CS);
                float v = s2 * (1.0f / CS) - m * m;
                mv[w][0] = m;
                mv[w][1] = rsqrtf(v + EPS);
            }
        }
        __syncthreads();
#pragma unroll
        for (int i = 0; i < 12; i++) {
            int idx = tid + 256 * i;
            int r = idx / CS, k = idx - r * CS;
            sn[r][k] = (sn[r][k] - mv[r][0]) * mv[r][1] * gs[k] + bs[k];
        }
        __syncthreads();
        int j = tid & 127;
        int h = tid >> 7;
        float a0 = 0.f, a1 = 0.f, a2 = 0.f, a3 = 0.f;
#pragma unroll 16
        for (int k = 0; k < CS; k++) {
            float wv = Ws[(size_t)k * CA + j];
            a0 = fmaf(sn[4*h  ][k], wv, a0);
            a1 = fmaf(sn[4*h+1][k], wv, a1);
            a2 = fmaf(sn[4*h+2][k], wv, a2);
            a3 = fmaf(sn[4*h+3][k], wv, a3);
        }
        g_ys[(size_t)(t0 + 4*h    ) * CA + j] = a0;
        g_ys[(size_t)(t0 + 4*h + 1) * CA + j] = a1;
        g_ys[(size_t)(t0 + 4*h + 2) * CA + j] = a2;
        g_ys[(size_t)(t0 + 4*h + 3) * CA + j] = a3;
        return;
    }

    if (bx < YS_BLOCKS + TOK_BLOCKS) {
        // prefetch cl into L2 (512 KB total)
        {
            int idx = (bx - YS_BLOCKS) * 256 + tid;
            if (idx < 4096) PREFETCH_L2(cl + (size_t)idx * 32);
        }
        int row0 = (bx - YS_BLOCKS) * 32;
#pragma unroll
        for (int i = 0; i < 32; i++) {
            float v = a2t[(size_t)(row0 + i) * T_DIM + tid];
            if (v > 0.5f) g_tok[row0 + i] = tid;
        }
        return;
    }

    // ---------- k_w: 32 rows/block; warp w owns k-slice [w*16, w*16+16) ----------
    // plm L2-prefetch: 67 MB / 2048 blocks = 256 lines/block = 1 line/thread
    {
        size_t line = ((size_t)(bx - YS_BLOCKS - TOK_BLOCKS) * 256 + tid);
        PREFETCH_L2(plm + line * 32);
    }

    __shared__ __align__(16) float GWs[CP * GWPAD];        // [j][k]
    __shared__ __align__(16) float zs[KW_ROWS * GWPAD];    // [row][k]
    __shared__ float rst[18][8][32];                       // [item][q8][row]
    __shared__ float BWs[CP], CgWs[CP];
    __shared__ float osm[KW_ROWS * 18];

    // phase 0: GW + folded constants
    {
        float* pbw = &rst[0][0][0];
        float* pcg = pbw + 256;
        int j = tid & 15;
        float pb = 0.f, pc = 0.f;
#pragma unroll
        for (int i = 0; i < 8; i++) {
            int idx = tid + 256 * i;
            int k = idx >> 4;
            float wv = Wz[idx];
            float gw = gz[k] * wv;
            GWs[j * GWPAD + k] = gw;
            pb = fmaf(bz[k], wv, pb);
            pc += gw;
        }
        pbw[tid] = pb;
        pcg[tid] = pc;
        __syncthreads();
        if (tid < CP) {
            float sb = 0.f, sc = 0.f;
#pragma unroll
            for (int i = 0; i < 16; i++) {
                sb += pbw[tid + 16 * i];
                sc += pcg[tid + 16 * i];
            }
            BWs[tid] = sb;
            CgWs[tid] = sc;
        }
    }

    // phase 1: stage z tile (32 rows x 128 floats), coalesced streaming loads
    {
        size_t row0 = (size_t)(bx - YS_BLOCKS - TOK_BLOCKS) * KW_ROWS;
        const float4* zg = (const float4*)(zij + row0 * CZ);
        float4* zs4 = (float4*)zs;
#pragma unroll
        for (int i = 0; i < 4; i++) {
            int idx = tid + 256 * i;
            int r = idx >> 5, c16 = idx & 31;
            zs4[r * 33 + c16] = __ldcs(&zg[idx]);
        }
    }
    __syncthreads();

    // phase 2: warp w = k-eighth, lane = row; GW reads warp-uniform
    {
        int w = tid >> 5, lane = tid & 31;
        const ulonglong2* zrow = (const ulonglong2*)(zs + lane * GWPAD);
        const ulonglong2* G = (const ulonglong2*)GWs;

        unsigned long long acc[CP];
#pragma unroll
        for (int j = 0; j < CP; j++) acc[j] = 0ull;
        unsigned long long sS = 0ull, sQ = 0ull;

#pragma unroll
        for (int c = 0; c < 4; c++) {
            int chunk = w * 4 + c;
            ulonglong2 zv = zrow[chunk];
            ADD2(sS, zv.x); ADD2(sS, zv.y);
            FMA2(sQ, zv.x, zv.x); FMA2(sQ, zv.y, zv.y);
#pragma unroll
            for (int j = 0; j < CP; j++) {
                ulonglong2 g = G[j * 33 + chunk];
                FMA2(acc[j], zv.x, g.x); FMA2(acc[j], zv.y, g.y);
            }
        }
#pragma unroll
        for (int j = 0; j < CP; j++) rst[j][w][lane] = hsum2(acc[j]);
        rst[16][w][lane] = hsum2(sS);
        rst[17][w][lane] = hsum2(sQ);
    }
    __syncthreads();

    // phase 3: reduce 8 k-slices
    {
        int row = tid & 31, jh = tid >> 5;
        float s1 = 0.f, s2 = 0.f, f0 = 0.f, f1 = 0.f;
#pragma unroll
        for (int q = 0; q < 8; q++) {
            f0 += rst[2*jh    ][q][row];
            f1 += rst[2*jh + 1][q][row];
            s1 += rst[16][q][row];
            s2 += rst[17][q][row];
        }
        float m  = s1 * (1.0f / CZ);
        float vv = s2 * (1.0f / CZ) - m * m;
        float ri = rsqrtf(vv + EPS);
        osm[row * 18 + 2*jh    ] = ri * (f0 - m * CgWs[2*jh    ]) + BWs[2*jh    ];
        osm[row * 18 + 2*jh + 1] = ri * (f1 - m * CgWs[2*jh + 1]) + BWs[2*jh + 1];
    }
    __syncthreads();

    // phase 4: coalesced write of 32x16 w tile
    {
        size_t row0 = (size_t)(bx - YS_BLOCKS - TOK_BLOCKS) * KW_ROWS;
        float2* wo = (float2*)(g_w + row0 * CP);
        int r = tid >> 3, jp = tid & 7;
        float2 v;
        v.x = osm[r * 18 + jp * 2];
        v.y = osm[r * 18 + jp * 2 + 1];
        wo[r * 8 + jp] = v;
    }
}

// ================= kernel B (round-9 champion, unchanged) =================
__global__ __launch_bounds__(256) void kernelB(
    const float* __restrict__ cl, const float* __restrict__ ql,
    const float* __restrict__ rl, const float* __restrict__ Wr,
    const float* __restrict__ plm,
    float* __restrict__ out_cl, float* __restrict__ out_ql,
    float* __restrict__ out_plm) {
    int tid = threadIdx.x;
    int bx = blockIdx.x;

    if (bx < 128) {
        int a = bx * 8 + (tid >> 5);
        int j4 = tid & 31;
        size_t idx = (size_t)a * 32 + j4;
        const float4* cl4 = (const float4*)cl;
        const float4* ql4 = (const float4*)ql;
        const float4* ys4 = (const float4*)g_ys;
        const float4* Wr4 = (const float4*)Wr;
        float4 c = cl4[idx];
        float4 qv = ql4[idx];
        float r0 = rl[a * 3], r1 = rl[a * 3 + 1], r2 = rl[a * 3 + 2];
        float4 w0 = Wr4[j4], w1 = Wr4[32 + j4], w2 = Wr4[64 + j4];
        float4 oq;
        oq.x = qv.x + r0 * w0.x + r1 * w1.x + r2 * w2.x;
        oq.y = qv.y + r0 * w0.y + r1 * w1.y + r2 * w2.y;
        oq.z = qv.z + r0 * w0.z + r1 * w1.z + r2 * w2.z;
        oq.w = qv.w + r0 * w0.w + r1 * w1.w + r2 * w2.w;
        ((float4*)out_ql)[idx] = oq;
        asm volatile("griddepcontrol.wait;" ::: "memory");
        int ta = g_tok[a];
        float4 y = ys4[(size_t)ta * 32 + j4];
        float4 oc;
        oc.x = c.x + y.x; oc.y = c.y + y.y; oc.z = c.z + y.z; oc.w = c.w + y.w;
        ((float4*)out_cl)[idx] = oc;
        return;
    }

    int pm = bx - 128;
    int a0 = (pm >> 4) * 8;
    int b = (pm & 15) * 64 + (tid >> 2);
    int c4 = tid & 3;
    const float4* p4 = (const float4*)plm;
    const float4* w4 = (const float4*)g_w;
    float4* o4 = (float4*)out_plm;

    float4 p[8];
#pragma unroll
    for (int i = 0; i < 8; i++)
        p[i] = p4[((size_t)(a0 + i) * A_DIM + b) * 4 + c4];   // L2-resident via prefetch

    asm volatile("griddepcontrol.wait;" ::: "memory");

    int tb = g_tok[b];
    int ta[8];
#pragma unroll
    for (int i = 0; i < 8; i++) ta[i] = g_tok[a0 + i];

    float4 w[8];
#pragma unroll
    for (int i = 0; i < 8; i++)
        w[i] = w4[((size_t)ta[i] * T_DIM + tb) * 4 + c4];
#pragma unroll
    for (int i = 0; i < 8; i++) {
        float4 o;
        o.x = p[i].x + w[i].x; o.y = p[i].y + w[i].y;
        o.z = p[i].z + w[i].z; o.w = p[i].w + w[i].w;
        __stcs(&o4[((size_t)(a0 + i) * A_DIM + b) * 4 + c4], o);
    }
}

extern "C" void kernel_launch(void* const* d_in, const int* in_sizes, int n_in,
                              void* d_out, int out_size) {
    const float* a2t     = (const float*)d_in[0];
    const float* cl      = (const float*)d_in[1];
    const float* plm     = (const float*)d_in[2];
    const float* ql      = (const float*)d_in[3];
    const float* s_trunk = (const float*)d_in[4];
    const float* zij     = (const float*)d_in[5];
    const float* rl      = (const float*)d_in[6];
    const float* ln_s_g  = (const float*)d_in[7];
    const float* ln_s_b  = (const float*)d_in[8];
    const float* Ws      = (const float*)d_in[9];
    const float* ln_z_g  = (const float*)d_in[10];
    const float* ln_z_b  = (const float*)d_in[11];
    const float* Wz      = (const float*)d_in[12];
    const float* Wr      = (const float*)d_in[13];
    float* out     = (float*)d_out;
    float* out_cl  = out;
    float* out_plm = out + A_DIM * CA;
    float* out_ql  = out_plm + (size_t)A_DIM * A_DIM * CP;

    kernelA<<<YS_BLOCKS + TOK_BLOCKS + KW_BLOCKS, 256>>>(
        zij, ln_z_g, ln_z_b, Wz, s_trunk, ln_s_g, ln_s_b, Ws, a2t,
        plm, cl, ql);

    {
        cudaLaunchConfig_t cfg = {};
        cfg.gridDim = dim3(128 + 2048);
        cfg.blockDim = dim3(256);
        cfg.dynamicSmemBytes = 0;
        cfg.stream = 0;
        cudaLaunchAttribute attrs[1];
        attrs[0].id = cudaLaunchAttributeProgrammaticStreamSerialization;
        attrs[0].val.programmaticStreamSerializationAllowed = 1;
        cfg.attrs = attrs;
        cfg.numAttrs = 1;
        cudaLaunchKernelEx(&cfg, kernelB, cl, ql, rl, Wr, plm,
                           out_cl, out_ql, out_plm);
    }
}